// round 1
// baseline (speedup 1.0000x reference)
#include <cuda_runtime.h>

#define BATCH 4
#define CDIM 256
#define NSEQ 2304          // 48*48
#define NHEADS 8
#define HDIM 32
#define ATT_SCALE 0.17677669529663687f   // 32^-0.5

#define BNC (BATCH * NSEQ * CDIM)

// Scratch (device globals; no allocation allowed)
__device__ float g_Q1[BNC], g_K1[BNC], g_V1[BNC];   // img-query branch
__device__ float g_Q2[BNC], g_K2[BNC], g_V2[BNC];   // radar-query branch
__device__ float g_O1[BNC], g_O2[BNC];              // attention outputs [b][n][c]

// ---------------------------------------------------------------------------
// Kernel 1: QKV projections.
//   A[n][c] = feat[b][c][n]  (feat is (B,C,H,W) => (B,C,N))
//   g=0: Q_img  = img_seq   @ Wq_img   (OUT=256) -> g_Q1[b][n][j]
//   g=1: KV_rad = radar_seq @ Wkv_radar(OUT=512) -> g_K1 / g_V1
//   g=2: Q_rad  = radar_seq @ Wq_radar (OUT=256) -> g_Q2
//   g=3: KV_img = img_seq   @ Wkv_img  (OUT=512) -> g_K2 / g_V2
// Column j of a KV product decomposes as j = pair*256 + head*32 + d.
// Tile: 64(n) x 64(j) x 16(k), 256 threads, 4x4 microtile.
// ---------------------------------------------------------------------------
__global__ __launch_bounds__(256) void gemm_qkv(
    const float* __restrict__ img, const float* __restrict__ radar,
    const float* __restrict__ Wqi, const float* __restrict__ Wkvr,
    const float* __restrict__ Wqr, const float* __restrict__ Wkvi)
{
    const int z = blockIdx.z;
    const int b = z >> 2;
    const int g = z & 3;
    const int OUT = (g & 1) ? 512 : 256;
    const int j0 = blockIdx.y * 64;
    if (j0 >= OUT) return;
    const int n0 = blockIdx.x * 64;

    const float* A = ((g == 0) || (g == 3)) ? img : radar;
    A += (size_t)b * CDIM * NSEQ;
    const float* W = (g == 0) ? Wqi : (g == 1) ? Wkvr : (g == 2) ? Wqr : Wkvi;

    __shared__ float As[16][64];
    __shared__ float Bs[16][64];

    const int tid = threadIdx.x;
    const int tx = tid & 15;   // j group
    const int ty = tid >> 4;   // n group

    float acc[4][4];
#pragma unroll
    for (int i = 0; i < 4; i++)
#pragma unroll
        for (int j = 0; j < 4; j++) acc[i][j] = 0.f;

    for (int k0 = 0; k0 < CDIM; k0 += 16) {
#pragma unroll
        for (int it = 0; it < 4; it++) {
            int idx = tid + it * 256;
            int kk = idx >> 6, mm = idx & 63;
            As[kk][mm] = A[(k0 + kk) * NSEQ + n0 + mm];       // coalesced over n
            Bs[kk][mm] = W[(k0 + kk) * OUT + j0 + mm];        // coalesced over j
        }
        __syncthreads();
#pragma unroll
        for (int kk = 0; kk < 16; kk++) {
            float4 a4 = *(const float4*)&As[kk][ty * 4];
            float4 b4 = *(const float4*)&Bs[kk][tx * 4];
            float av[4] = {a4.x, a4.y, a4.z, a4.w};
            float bv[4] = {b4.x, b4.y, b4.z, b4.w};
#pragma unroll
            for (int i = 0; i < 4; i++)
#pragma unroll
                for (int j = 0; j < 4; j++)
                    acc[i][j] = fmaf(av[i], bv[j], acc[i][j]);
        }
        __syncthreads();
    }

    // Destination (whole 64-wide j-tile lands in one of K or V region)
    float* dst;
    int jo = j0;
    if (g == 0)      dst = g_Q1;
    else if (g == 2) dst = g_Q2;
    else if (g == 1) { if (j0 < 256) dst = g_K1; else { dst = g_V1; jo = j0 - 256; } }
    else             { if (j0 < 256) dst = g_K2; else { dst = g_V2; jo = j0 - 256; } }

#pragma unroll
    for (int i = 0; i < 4; i++) {
        int n = n0 + ty * 4 + i;
        float4 v = make_float4(acc[i][0], acc[i][1], acc[i][2], acc[i][3]);
        *(float4*)&dst[((size_t)b * NSEQ + n) * CDIM + jo + tx * 4] = v;
    }
}

// ---------------------------------------------------------------------------
// Kernel 2: flash attention.
// Block = 128 threads = 4 warps; handles 32 query rows for one (b, head, branch).
// Each warp owns 8 rows. Iterates 72 key tiles of 32.
// SCALE and the uncertainty temperature uw (img branch only) are folded into Q.
// ---------------------------------------------------------------------------
__global__ __launch_bounds__(128) void attn(const float* __restrict__ umask)
{
    const int qt = blockIdx.x;            // 0..71
    const int h  = blockIdx.y;            // 0..7
    const int z  = blockIdx.z;            // 0..7
    const int b  = z >> 1;
    const int br = z & 1;                 // 0 = img-query branch, 1 = radar-query

    const float* Q = br ? g_Q2 : g_Q1;
    const float* K = br ? g_K2 : g_K1;
    const float* V = br ? g_V2 : g_V1;
    float*       O = br ? g_O2 : g_O1;

    __shared__ float Qs[32][33];
    __shared__ float Kt[32][33];   // transposed: Kt[c][key]
    __shared__ float Vs[32][32];
    __shared__ float Ps[32][33];

    const int tid  = threadIdx.x;
    const int lane = tid & 31;
    const int warp = tid >> 5;
    const int n0   = qt * 32;
    const size_t base_q = ((size_t)b * NSEQ + n0) * CDIM + h * HDIM;

    // Load + pre-scale Q tile
    for (int idx = tid; idx < 1024; idx += 128) {
        int r = idx >> 5, c = idx & 31;
        float uw = 1.0f;
        if (br == 0) uw = 1.0f / (umask[b * NSEQ + n0 + r] + 1e-6f);
        Qs[r][c] = Q[base_q + (size_t)r * CDIM + c] * (ATT_SCALE * uw);
    }
    __syncthreads();

    float mrow[8], lrow[8], acc[8];
#pragma unroll
    for (int i = 0; i < 8; i++) { mrow[i] = -1e30f; lrow[i] = 0.f; acc[i] = 0.f; }

    for (int kt = 0; kt < NSEQ / 32; kt++) {
        const int m0 = kt * 32;
        const size_t base_k = ((size_t)b * NSEQ + m0) * CDIM + h * HDIM;
        for (int idx = tid; idx < 1024; idx += 128) {
            int key = idx >> 5, c = idx & 31;
            Kt[c][key] = K[base_k + (size_t)key * CDIM + c];
            Vs[key][c] = V[base_k + (size_t)key * CDIM + c];
        }
        __syncthreads();

        // S = Q K^T, online softmax (lane owns a key)
#pragma unroll
        for (int r8 = 0; r8 < 8; r8++) {
            const int r = warp * 8 + r8;
            float s = 0.f;
#pragma unroll
            for (int c = 0; c < 32; c++) s = fmaf(Qs[r][c], Kt[c][lane], s);
            float mx = s;
#pragma unroll
            for (int off = 16; off > 0; off >>= 1)
                mx = fmaxf(mx, __shfl_xor_sync(0xffffffffu, mx, off));
            float mnew = fmaxf(mrow[r8], mx);
            float p = __expf(s - mnew);
            float sum = p;
#pragma unroll
            for (int off = 16; off > 0; off >>= 1)
                sum += __shfl_xor_sync(0xffffffffu, sum, off);
            float alpha = __expf(mrow[r8] - mnew);
            lrow[r8] = lrow[r8] * alpha + sum;
            mrow[r8] = mnew;
            acc[r8] *= alpha;
            Ps[r][lane] = p;
        }
        __syncwarp();

        // O += P V (lane owns an output dim d)
#pragma unroll
        for (int r8 = 0; r8 < 8; r8++) {
            const int r = warp * 8 + r8;
            float a = acc[r8];
#pragma unroll
            for (int key = 0; key < 32; key++)
                a = fmaf(Ps[r][key], Vs[key][lane], a);
            acc[r8] = a;
        }
        __syncthreads();
    }

#pragma unroll
    for (int r8 = 0; r8 < 8; r8++) {
        int n = n0 + warp * 8 + r8;
        O[((size_t)b * NSEQ + n) * CDIM + h * HDIM + lane] = acc[r8] / lrow[r8];
    }
}

// ---------------------------------------------------------------------------
// Kernel 3: output projection + bias, written transposed to (B,C,H,W).
// A = g_O[b] row-major [N][256]; out[b][c][n] (img half first, radar at +B*C*N).
// ---------------------------------------------------------------------------
__global__ __launch_bounds__(256) void gemm_proj(
    const float* __restrict__ Wpi, const float* __restrict__ bpi,
    const float* __restrict__ Wpr, const float* __restrict__ bpr,
    float* __restrict__ out)
{
    const int z = blockIdx.z;
    const int b = z >> 1;
    const int br = z & 1;
    const float* A = (br ? g_O2 : g_O1) + (size_t)b * NSEQ * CDIM;
    const float* W = br ? Wpr : Wpi;
    const float* bias = br ? bpr : bpi;
    float* O = out + (br ? (size_t)BATCH * CDIM * NSEQ : 0) + (size_t)b * CDIM * NSEQ;

    const int n0 = blockIdx.x * 64;
    const int j0 = blockIdx.y * 64;

    __shared__ float As[64][17];   // [n][k], padded
    __shared__ float Bs[16][64];

    const int tid = threadIdx.x;
    const int tx = tid & 15, ty = tid >> 4;

    float acc[4][4];
#pragma unroll
    for (int i = 0; i < 4; i++)
#pragma unroll
        for (int j = 0; j < 4; j++) acc[i][j] = 0.f;

    for (int k0 = 0; k0 < CDIM; k0 += 16) {
#pragma unroll
        for (int it = 0; it < 4; it++) {
            int idx = tid + it * 256;
            int mm = idx >> 4, kk = idx & 15;
            As[mm][kk] = A[(size_t)(n0 + mm) * CDIM + k0 + kk];
        }
#pragma unroll
        for (int it = 0; it < 4; it++) {
            int idx = tid + it * 256;
            int kk = idx >> 6, jj = idx & 63;
            Bs[kk][jj] = W[(k0 + kk) * CDIM + j0 + jj];
        }
        __syncthreads();
#pragma unroll
        for (int kk = 0; kk < 16; kk++) {
            float4 b4 = *(const float4*)&Bs[kk][tx * 4];
            float bv[4] = {b4.x, b4.y, b4.z, b4.w};
            float av[4];
#pragma unroll
            for (int i = 0; i < 4; i++) av[i] = As[ty * 4 + i][kk];
#pragma unroll
            for (int i = 0; i < 4; i++)
#pragma unroll
                for (int j = 0; j < 4; j++)
                    acc[i][j] = fmaf(av[i], bv[j], acc[i][j]);
        }
        __syncthreads();
    }

#pragma unroll
    for (int jj = 0; jj < 4; jj++) {
        int j = j0 + tx * 4 + jj;
        float bval = bias[j];
        float4 v = make_float4(acc[0][jj] + bval, acc[1][jj] + bval,
                               acc[2][jj] + bval, acc[3][jj] + bval);
        *(float4*)&O[(size_t)j * NSEQ + n0 + ty * 4] = v;   // contiguous over n
    }
}

// ---------------------------------------------------------------------------
extern "C" void kernel_launch(void* const* d_in, const int* in_sizes, int n_in,
                              void* d_out, int out_size)
{
    const float* img   = (const float*)d_in[0];
    const float* radar = (const float*)d_in[1];
    const float* mask  = (const float*)d_in[2];
    const float* Wqi   = (const float*)d_in[3];
    const float* Wkvr  = (const float*)d_in[4];
    const float* Wqr   = (const float*)d_in[5];
    const float* Wkvi  = (const float*)d_in[6];
    const float* Wpi   = (const float*)d_in[7];
    const float* bpi   = (const float*)d_in[8];
    const float* Wpr   = (const float*)d_in[9];
    const float* bpr   = (const float*)d_in[10];
    float* out = (float*)d_out;

    gemm_qkv<<<dim3(NSEQ / 64, 8, BATCH * 4), 256>>>(img, radar, Wqi, Wkvr, Wqr, Wkvi);
    attn<<<dim3(NSEQ / 32, NHEADS, BATCH * 2), 128>>>(mask);
    gemm_proj<<<dim3(NSEQ / 64, CDIM / 64, BATCH * 2), 256>>>(Wpi, bpi, Wpr, bpr, out);
}

// round 12
// speedup vs baseline: 3.2006x; 3.2006x over previous
#include <cuda_runtime.h>
#include <cuda_fp16.h>
#include <cstdint>

#define BATCH 4
#define CDIM 256
#define NSEQ 2304          // 48*48
#define NHEADS 8
#define HDIM 32
#define ATT_SCALE 0.17677669529663687f   // 32^-0.5

#define BNC (BATCH * NSEQ * CDIM)
#define QT 64              // queries per block (16 per warp)
#define KT 64              // keys per tile
#define NKT (NSEQ / KT)    // 36 key tiles

// Scratch (device globals; no allocation allowed)
__device__ float g_Q1[BNC], g_K1[BNC], g_V1[BNC];   // img-query branch
__device__ float g_Q2[BNC], g_K2[BNC], g_V2[BNC];   // radar-query branch
__device__ float g_O1[BNC], g_O2[BNC];              // attention outputs [b][n][c]

// fp16 split of a float pair: x = (hi(f0)|hi(f1)<<16), y = (lo(f0)|lo(f1)<<16)
__device__ __forceinline__ uint2 split2(float f0, float f1) {
    __half h0 = __float2half_rn(f0), h1 = __float2half_rn(f1);
    float r0 = f0 - __half2float(h0), r1 = f1 - __half2float(h1);
    __half g0 = __float2half_rn(r0), g1 = __float2half_rn(r1);
    uint2 o;
    o.x = (uint32_t)__half_as_ushort(h0) | ((uint32_t)__half_as_ushort(h1) << 16);
    o.y = (uint32_t)__half_as_ushort(g0) | ((uint32_t)__half_as_ushort(g1) << 16);
    return o;
}

// m16n8k16 row.col f32 += f16*f16 (accumulate in place)
__device__ __forceinline__ void mma16816(float* c, const uint32_t* a,
                                         uint32_t b0, uint32_t b1) {
    asm volatile(
        "mma.sync.aligned.m16n8k16.row.col.f32.f16.f16.f32 "
        "{%0,%1,%2,%3}, {%4,%5,%6,%7}, {%8,%9}, {%0,%1,%2,%3};"
        : "+f"(c[0]), "+f"(c[1]), "+f"(c[2]), "+f"(c[3])
        : "r"(a[0]), "r"(a[1]), "r"(a[2]), "r"(a[3]), "r"(b0), "r"(b1));
}

// ===========================================================================
// Kernel 1: QKV projections (unchanged, known good: 191us)
// ===========================================================================
__global__ __launch_bounds__(256) void gemm_qkv(
    const float* __restrict__ img, const float* __restrict__ radar,
    const float* __restrict__ Wqi, const float* __restrict__ Wkvr,
    const float* __restrict__ Wqr, const float* __restrict__ Wkvi)
{
    const int z = blockIdx.z;
    const int b = z >> 2;
    const int g = z & 3;
    const int OUT = (g & 1) ? 512 : 256;
    const int j0 = blockIdx.y * 64;
    if (j0 >= OUT) return;
    const int n0 = blockIdx.x * 64;

    const float* A = ((g == 0) || (g == 3)) ? img : radar;
    A += (size_t)b * CDIM * NSEQ;
    const float* W = (g == 0) ? Wqi : (g == 1) ? Wkvr : (g == 2) ? Wqr : Wkvi;

    __shared__ float As[16][64];
    __shared__ float Bs[16][64];

    const int tid = threadIdx.x;
    const int tx = tid & 15;
    const int ty = tid >> 4;

    float acc[4][4];
#pragma unroll
    for (int i = 0; i < 4; i++)
#pragma unroll
        for (int j = 0; j < 4; j++) acc[i][j] = 0.f;

    for (int k0 = 0; k0 < CDIM; k0 += 16) {
#pragma unroll
        for (int it = 0; it < 4; it++) {
            int idx = tid + it * 256;
            int kk = idx >> 6, mm = idx & 63;
            As[kk][mm] = A[(k0 + kk) * NSEQ + n0 + mm];
            Bs[kk][mm] = W[(k0 + kk) * OUT + j0 + mm];
        }
        __syncthreads();
#pragma unroll
        for (int kk = 0; kk < 16; kk++) {
            float4 a4 = *(const float4*)&As[kk][ty * 4];
            float4 b4 = *(const float4*)&Bs[kk][tx * 4];
            float av[4] = {a4.x, a4.y, a4.z, a4.w};
            float bv[4] = {b4.x, b4.y, b4.z, b4.w};
#pragma unroll
            for (int i = 0; i < 4; i++)
#pragma unroll
                for (int j = 0; j < 4; j++)
                    acc[i][j] = fmaf(av[i], bv[j], acc[i][j]);
        }
        __syncthreads();
    }

    float* dst;
    int jo = j0;
    if (g == 0)      dst = g_Q1;
    else if (g == 2) dst = g_Q2;
    else if (g == 1) { if (j0 < 256) dst = g_K1; else { dst = g_V1; jo = j0 - 256; } }
    else             { if (j0 < 256) dst = g_K2; else { dst = g_V2; jo = j0 - 256; } }

#pragma unroll
    for (int i = 0; i < 4; i++) {
        int n = n0 + ty * 4 + i;
        float4 v = make_float4(acc[i][0], acc[i][1], acc[i][2], acc[i][3]);
        *(float4*)&dst[((size_t)b * NSEQ + n) * CDIM + jo + tx * 4] = v;
    }
}

// ===========================================================================
// Kernel 2: flash attention on mma.sync.m16n8k16 (HMMA), fp16 split-pair.
// Block = 128 thr = 4 warps; warp owns 16 query rows; 64 queries per block.
// Online softmax; P stays in registers (S C-frag == PV A-frag layout).
// SMEM per tile: K[key][d] hi/lo (stride 40 halves, conflict-free B loads),
//                V^T[d][key] hi/lo (stride 72 halves, conflict-free).
// ===========================================================================
#define KS_STRIDE 40
#define VT_STRIDE 72

__global__ __launch_bounds__(128) void attn_mma(const float* __restrict__ umask)
{
    __shared__ alignas(16) uint16_t sK_hi[KT * KS_STRIDE];
    __shared__ alignas(16) uint16_t sK_lo[KT * KS_STRIDE];
    __shared__ alignas(16) uint16_t sV_hi[HDIM * VT_STRIDE];
    __shared__ alignas(16) uint16_t sV_lo[HDIM * VT_STRIDE];

    const int tid  = threadIdx.x;
    const int lane = tid & 31;
    const int w    = tid >> 5;
    const int qt = blockIdx.x;            // 0..35
    const int hh = blockIdx.y;            // 0..7
    const int z  = blockIdx.z;            // 0..7
    const int b  = z >> 1;
    const int br = z & 1;

    const float* Q = br ? g_Q2 : g_Q1;
    const float* K = br ? g_K2 : g_K1;
    const float* V = br ? g_V2 : g_V1;
    float*       O = br ? g_O2 : g_O1;

    const int n0 = qt * QT;
    const int g  = lane >> 2;             // row group within fragment
    const int qr = (lane & 3) * 2;        // quad-pair column base
    const int r0 = n0 + w * 16 + g;
    const int r1 = r0 + 8;

    // uncertainty temperature (fp32, applied AFTER the S MMA)
    float uw0 = 1.f, uw1 = 1.f;
    if (br == 0) {
        uw0 = 1.0f / (umask[b * NSEQ + r0] + 1e-6f);
        uw1 = 1.0f / (umask[b * NSEQ + r1] + 1e-6f);
    }

    // Q A-fragments (2 k-steps of d), hi/lo, ATT_SCALE folded (safe range)
    uint32_t Ah[2][4], Al[2][4];
    {
        const float* q0 = Q + ((size_t)b * NSEQ + r0) * CDIM + hh * HDIM;
        const float* q1 = Q + ((size_t)b * NSEQ + r1) * CDIM + hh * HDIM;
#pragma unroll
        for (int s = 0; s < 2; s++) {
            int db = s * 16 + qr;
            float2 f; uint2 u;
            f = *(const float2*)(q0 + db);
            u = split2(f.x * ATT_SCALE, f.y * ATT_SCALE); Ah[s][0] = u.x; Al[s][0] = u.y;
            f = *(const float2*)(q1 + db);
            u = split2(f.x * ATT_SCALE, f.y * ATT_SCALE); Ah[s][1] = u.x; Al[s][1] = u.y;
            f = *(const float2*)(q0 + db + 8);
            u = split2(f.x * ATT_SCALE, f.y * ATT_SCALE); Ah[s][2] = u.x; Al[s][2] = u.y;
            f = *(const float2*)(q1 + db + 8);
            u = split2(f.x * ATT_SCALE, f.y * ATT_SCALE); Ah[s][3] = u.x; Al[s][3] = u.y;
        }
    }

    float m0 = -1e30f, m1 = -1e30f, l0 = 0.f, l1 = 0.f;
    float Oc[4][4];
#pragma unroll
    for (int f = 0; f < 4; f++)
#pragma unroll
        for (int i = 0; i < 4; i++) Oc[f][i] = 0.f;

    for (int kt = 0; kt < NKT; kt++) {
        const size_t kb = ((size_t)b * NSEQ + kt * KT) * CDIM + hh * HDIM;

        // ---- load + split K,V tile (thread: key=tid/2, half of d) ----
        {
            const int key = tid >> 1, dh = (tid & 1) * 16;
            const float4* ksrc = (const float4*)(K + kb + (size_t)key * CDIM + dh);
            const float4* vsrc = (const float4*)(V + kb + (size_t)key * CDIM + dh);
            uint32_t* kh = (uint32_t*)(sK_hi + key * KS_STRIDE + dh);
            uint32_t* kl = (uint32_t*)(sK_lo + key * KS_STRIDE + dh);
#pragma unroll
            for (int i = 0; i < 4; i++) {
                float4 f = ksrc[i];
                uint2 u01 = split2(f.x, f.y), u23 = split2(f.z, f.w);
                kh[i * 2] = u01.x; kh[i * 2 + 1] = u23.x;
                kl[i * 2] = u01.y; kl[i * 2 + 1] = u23.y;
                float4 v = vsrc[i];
                int d = dh + i * 4;
                uint2 w01 = split2(v.x, v.y), w23 = split2(v.z, v.w);
                sV_hi[(d + 0) * VT_STRIDE + key] = (uint16_t)(w01.x & 0xFFFF);
                sV_hi[(d + 1) * VT_STRIDE + key] = (uint16_t)(w01.x >> 16);
                sV_hi[(d + 2) * VT_STRIDE + key] = (uint16_t)(w23.x & 0xFFFF);
                sV_hi[(d + 3) * VT_STRIDE + key] = (uint16_t)(w23.x >> 16);
                sV_lo[(d + 0) * VT_STRIDE + key] = (uint16_t)(w01.y & 0xFFFF);
                sV_lo[(d + 1) * VT_STRIDE + key] = (uint16_t)(w01.y >> 16);
                sV_lo[(d + 2) * VT_STRIDE + key] = (uint16_t)(w23.y & 0xFFFF);
                sV_lo[(d + 3) * VT_STRIDE + key] = (uint16_t)(w23.y >> 16);
            }
        }
        __syncthreads();

        // ---- S = Q K^T (split: AhKh + AhKl + AlKh), fp32 accum ----
        float Sc[8][4];
#pragma unroll
        for (int f = 0; f < 8; f++)
#pragma unroll
            for (int i = 0; i < 4; i++) Sc[f][i] = 0.f;
#pragma unroll
        for (int f = 0; f < 8; f++) {
#pragma unroll
            for (int s = 0; s < 2; s++) {
                int idx = (f * 8 + g) * KS_STRIDE + s * 16 + qr;
                uint32_t bh0 = *(const uint32_t*)(sK_hi + idx);
                uint32_t bh1 = *(const uint32_t*)(sK_hi + idx + 8);
                uint32_t bl0 = *(const uint32_t*)(sK_lo + idx);
                uint32_t bl1 = *(const uint32_t*)(sK_lo + idx + 8);
                mma16816(Sc[f], Ah[s], bh0, bh1);
                mma16816(Sc[f], Ah[s], bl0, bl1);
                mma16816(Sc[f], Al[s], bh0, bh1);
            }
        }

        // ---- uw scale + online softmax (rows live in one quad) ----
        float mx0 = -1e30f, mx1 = -1e30f;
#pragma unroll
        for (int f = 0; f < 8; f++) {
            Sc[f][0] *= uw0; Sc[f][1] *= uw0;
            Sc[f][2] *= uw1; Sc[f][3] *= uw1;
            mx0 = fmaxf(mx0, fmaxf(Sc[f][0], Sc[f][1]));
            mx1 = fmaxf(mx1, fmaxf(Sc[f][2], Sc[f][3]));
        }
        mx0 = fmaxf(mx0, __shfl_xor_sync(0xffffffffu, mx0, 1));
        mx0 = fmaxf(mx0, __shfl_xor_sync(0xffffffffu, mx0, 2));
        mx1 = fmaxf(mx1, __shfl_xor_sync(0xffffffffu, mx1, 1));
        mx1 = fmaxf(mx1, __shfl_xor_sync(0xffffffffu, mx1, 2));
        float mn0 = fmaxf(m0, mx0), mn1 = fmaxf(m1, mx1);
        float a0 = __expf(m0 - mn0), a1 = __expf(m1 - mn1);
        m0 = mn0; m1 = mn1;
#pragma unroll
        for (int f = 0; f < 4; f++) {
            Oc[f][0] *= a0; Oc[f][1] *= a0;
            Oc[f][2] *= a1; Oc[f][3] *= a1;
        }
        float s0 = 0.f, s1 = 0.f;
#pragma unroll
        for (int f = 0; f < 8; f++) {
            Sc[f][0] = __expf(Sc[f][0] - m0); s0 += Sc[f][0];
            Sc[f][1] = __expf(Sc[f][1] - m0); s0 += Sc[f][1];
            Sc[f][2] = __expf(Sc[f][2] - m1); s1 += Sc[f][2];
            Sc[f][3] = __expf(Sc[f][3] - m1); s1 += Sc[f][3];
        }
        s0 += __shfl_xor_sync(0xffffffffu, s0, 1);
        s0 += __shfl_xor_sync(0xffffffffu, s0, 2);
        s1 += __shfl_xor_sync(0xffffffffu, s1, 1);
        s1 += __shfl_xor_sync(0xffffffffu, s1, 2);
        l0 = l0 * a0 + s0;
        l1 = l1 * a1 + s1;

        // ---- O += P V (S C-frags reinterpret directly as PV A-frags) ----
#pragma unroll
        for (int j = 0; j < 4; j++) {
            uint32_t Ph[4], Pl[4];
            uint2 u;
            u = split2(Sc[2 * j][0], Sc[2 * j][1]);         Ph[0] = u.x; Pl[0] = u.y;
            u = split2(Sc[2 * j][2], Sc[2 * j][3]);         Ph[1] = u.x; Pl[1] = u.y;
            u = split2(Sc[2 * j + 1][0], Sc[2 * j + 1][1]); Ph[2] = u.x; Pl[2] = u.y;
            u = split2(Sc[2 * j + 1][2], Sc[2 * j + 1][3]); Ph[3] = u.x; Pl[3] = u.y;
#pragma unroll
            for (int f = 0; f < 4; f++) {
                int idx = (f * 8 + g) * VT_STRIDE + j * 16 + qr;
                uint32_t bh0 = *(const uint32_t*)(sV_hi + idx);
                uint32_t bh1 = *(const uint32_t*)(sV_hi + idx + 8);
                uint32_t bl0 = *(const uint32_t*)(sV_lo + idx);
                uint32_t bl1 = *(const uint32_t*)(sV_lo + idx + 8);
                mma16816(Oc[f], Ph, bh0, bh1);
                mma16816(Oc[f], Ph, bl0, bl1);
                mma16816(Oc[f], Pl, bh0, bh1);
            }
        }
        __syncthreads();
    }

    // ---- epilogue ----
    const float i0 = 1.0f / l0, i1 = 1.0f / l1;
    float* o0 = O + ((size_t)b * NSEQ + r0) * CDIM + hh * HDIM;
    float* o1 = O + ((size_t)b * NSEQ + r1) * CDIM + hh * HDIM;
#pragma unroll
    for (int f = 0; f < 4; f++) {
        int c = f * 8 + qr;
        *(float2*)(o0 + c) = make_float2(Oc[f][0] * i0, Oc[f][1] * i0);
        *(float2*)(o1 + c) = make_float2(Oc[f][2] * i1, Oc[f][3] * i1);
    }
}

// ===========================================================================
// Kernel 3: output projection + bias, written transposed to (B,C,H,W)
// ===========================================================================
__global__ __launch_bounds__(256) void gemm_proj(
    const float* __restrict__ Wpi, const float* __restrict__ bpi,
    const float* __restrict__ Wpr, const float* __restrict__ bpr,
    float* __restrict__ out)
{
    const int z = blockIdx.z;
    const int b = z >> 1;
    const int br = z & 1;
    const float* A = (br ? g_O2 : g_O1) + (size_t)b * NSEQ * CDIM;
    const float* W = br ? Wpr : Wpi;
    const float* bias = br ? bpr : bpi;
    float* O = out + (br ? (size_t)BATCH * CDIM * NSEQ : 0) + (size_t)b * CDIM * NSEQ;

    const int n0 = blockIdx.x * 64;
    const int j0 = blockIdx.y * 64;

    __shared__ float As[64][17];
    __shared__ float Bs[16][64];

    const int tid = threadIdx.x;
    const int tx = tid & 15, ty = tid >> 4;

    float acc[4][4];
#pragma unroll
    for (int i = 0; i < 4; i++)
#pragma unroll
        for (int j = 0; j < 4; j++) acc[i][j] = 0.f;

    for (int k0 = 0; k0 < CDIM; k0 += 16) {
#pragma unroll
        for (int it = 0; it < 4; it++) {
            int idx = tid + it * 256;
            int mm = idx >> 4, kk = idx & 15;
            As[mm][kk] = A[(size_t)(n0 + mm) * CDIM + k0 + kk];
        }
#pragma unroll
        for (int it = 0; it < 4; it++) {
            int idx = tid + it * 256;
            int kk = idx >> 6, jj = idx & 63;
            Bs[kk][jj] = W[(k0 + kk) * CDIM + j0 + jj];
        }
        __syncthreads();
#pragma unroll
        for (int kk = 0; kk < 16; kk++) {
            float4 b4 = *(const float4*)&Bs[kk][tx * 4];
            float bv[4] = {b4.x, b4.y, b4.z, b4.w};
            float av[4];
#pragma unroll
            for (int i = 0; i < 4; i++) av[i] = As[ty * 4 + i][kk];
#pragma unroll
            for (int i = 0; i < 4; i++)
#pragma unroll
                for (int j = 0; j < 4; j++)
                    acc[i][j] = fmaf(av[i], bv[j], acc[i][j]);
        }
        __syncthreads();
    }

#pragma unroll
    for (int jj = 0; jj < 4; jj++) {
        int j = j0 + tx * 4 + jj;
        float bval = bias[j];
        float4 v = make_float4(acc[0][jj] + bval, acc[1][jj] + bval,
                               acc[2][jj] + bval, acc[3][jj] + bval);
        *(float4*)&O[(size_t)j * NSEQ + n0 + ty * 4] = v;
    }
}

// ===========================================================================
extern "C" void kernel_launch(void* const* d_in, const int* in_sizes, int n_in,
                              void* d_out, int out_size)
{
    const float* img   = (const float*)d_in[0];
    const float* radar = (const float*)d_in[1];
    const float* mask  = (const float*)d_in[2];
    const float* Wqi   = (const float*)d_in[3];
    const float* Wkvr  = (const float*)d_in[4];
    const float* Wqr   = (const float*)d_in[5];
    const float* Wkvi  = (const float*)d_in[6];
    const float* Wpi   = (const float*)d_in[7];
    const float* bpi   = (const float*)d_in[8];
    const float* Wpr   = (const float*)d_in[9];
    const float* bpr   = (const float*)d_in[10];
    float* out = (float*)d_out;

    gemm_qkv<<<dim3(NSEQ / 64, 8, BATCH * 4), 256>>>(img, radar, Wqi, Wkvr, Wqr, Wkvi);
    attn_mma<<<dim3(NSEQ / QT, NHEADS, BATCH * 2), 128>>>(mask);
    gemm_proj<<<dim3(NSEQ / 64, CDIM / 64, BATCH * 2), 256>>>(Wpi, bpi, Wpr, bpr, out);
}

// round 15
// speedup vs baseline: 3.2722x; 1.0224x over previous
#include <cuda_runtime.h>
#include <cuda_fp16.h>
#include <cstdint>

#define BATCH 4
#define CDIM 256
#define NSEQ 2304          // 48*48
#define NHEADS 8
#define HDIM 32
#define ATT_SCALE 0.17677669529663687f   // 32^-0.5

#define BNC (BATCH * NSEQ * CDIM)
#define QT 64              // queries per block (16 per warp)
#define KT 64              // keys per tile
#define NKT (NSEQ / KT)    // 36 key tiles

// Scratch (device globals; no allocation allowed)
__device__ float g_Q1[BNC], g_K1[BNC], g_V1[BNC];   // img-query branch
__device__ float g_Q2[BNC], g_K2[BNC], g_V2[BNC];   // radar-query branch
__device__ float g_O1[BNC], g_O2[BNC];              // attention outputs [b][n][c]

// fp16 split of a float pair: x = (hi(f0)|hi(f1)<<16), y = (lo(f0)|lo(f1)<<16)
__device__ __forceinline__ uint2 split2(float f0, float f1) {
    __half h0 = __float2half_rn(f0), h1 = __float2half_rn(f1);
    float r0 = f0 - __half2float(h0), r1 = f1 - __half2float(h1);
    __half g0 = __float2half_rn(r0), g1 = __float2half_rn(r1);
    uint2 o;
    o.x = (uint32_t)__half_as_ushort(h0) | ((uint32_t)__half_as_ushort(h1) << 16);
    o.y = (uint32_t)__half_as_ushort(g0) | ((uint32_t)__half_as_ushort(g1) << 16);
    return o;
}
__device__ __forceinline__ uint2 splitf(float f) {   // single value, halves in low 16
    __half h = __float2half_rn(f);
    __half l = __float2half_rn(f - __half2float(h));
    uint2 o;
    o.x = (uint32_t)__half_as_ushort(h);
    o.y = (uint32_t)__half_as_ushort(l);
    return o;
}

// m16n8k16 row.col f32 += f16*f16 (accumulate in place)
__device__ __forceinline__ void mma16816(float* c, const uint32_t* a,
                                         uint32_t b0, uint32_t b1) {
    asm volatile(
        "mma.sync.aligned.m16n8k16.row.col.f32.f16.f16.f32 "
        "{%0,%1,%2,%3}, {%4,%5,%6,%7}, {%8,%9}, {%0,%1,%2,%3};"
        : "+f"(c[0]), "+f"(c[1]), "+f"(c[2]), "+f"(c[3])
        : "r"(a[0]), "r"(a[1]), "r"(a[2]), "r"(a[3]), "r"(b0), "r"(b1));
}

// ===========================================================================
// Kernel 1: QKV projections on HMMA (split-pair fp16, fp32 accum).
// Block 128 thr = 4 warps; tile 64n x 64j; K-chunks of 32.
// smem: A[n][k] and W^T[j][k] as halves, stride 42 (2-way max conflicts).
// ===========================================================================
#define QS 42

__global__ __launch_bounds__(128) void gemm_qkv_mma(
    const float* __restrict__ img, const float* __restrict__ radar,
    const float* __restrict__ Wqi, const float* __restrict__ Wkvr,
    const float* __restrict__ Wqr, const float* __restrict__ Wkvi)
{
    __shared__ alignas(16) uint16_t sA_hi[64 * QS];
    __shared__ alignas(16) uint16_t sA_lo[64 * QS];
    __shared__ alignas(16) uint16_t sB_hi[64 * QS];
    __shared__ alignas(16) uint16_t sB_lo[64 * QS];

    const int z = blockIdx.z;
    const int b = z >> 2;
    const int g = z & 3;
    const int OUT = (g & 1) ? 512 : 256;
    const int j0 = blockIdx.y * 64;
    if (j0 >= OUT) return;
    const int n0 = blockIdx.x * 64;

    const float* A = ((g == 0) || (g == 3)) ? img : radar;
    A += (size_t)b * CDIM * NSEQ;
    const float* W = (g == 0) ? Wqi : (g == 1) ? Wkvr : (g == 2) ? Wqr : Wkvi;

    const int tid  = threadIdx.x;
    const int lane = tid & 31;
    const int w    = tid >> 5;
    const int gq   = lane >> 2;
    const int qr   = (lane & 3) * 2;

    const int kr = tid >> 4;          // 0..7 (k row within chunk)
    const int n4 = (tid & 15) * 4;    // 4-wide column group

    float Oc[8][4];
#pragma unroll
    for (int f = 0; f < 8; f++)
#pragma unroll
        for (int i = 0; i < 4; i++) Oc[f][i] = 0.f;

    for (int k0 = 0; k0 < CDIM; k0 += 32) {
        // ---- stage A (feat[k][n] -> sA[n][k]) and W (W[k][j] -> sB[j][k]) ----
#pragma unroll
        for (int it = 0; it < 4; it++) {
            int k = kr + it * 8;
            float4 fa = *(const float4*)&A[(size_t)(k0 + k) * NSEQ + n0 + n4];
            float4 fw = *(const float4*)&W[(size_t)(k0 + k) * OUT + j0 + n4];
            const float av[4] = {fa.x, fa.y, fa.z, fa.w};
            const float wv[4] = {fw.x, fw.y, fw.z, fw.w};
#pragma unroll
            for (int e = 0; e < 4; e++) {
                uint2 ua = splitf(av[e]);
                uint2 uw2 = splitf(wv[e]);
                int ia = (n4 + e) * QS + k;
                sA_hi[ia] = (uint16_t)ua.x; sA_lo[ia] = (uint16_t)ua.y;
                sB_hi[ia] = (uint16_t)uw2.x; sB_lo[ia] = (uint16_t)uw2.y;
            }
        }
        __syncthreads();

        // ---- 2 k-steps of 16 ----
#pragma unroll
        for (int s = 0; s < 2; s++) {
            const int kb = s * 16;
            const int r0 = w * 16 + gq;
            uint32_t Ah[4], Al[4];
            Ah[0] = *(const uint32_t*)&sA_hi[r0 * QS + kb + qr];
            Ah[1] = *(const uint32_t*)&sA_hi[(r0 + 8) * QS + kb + qr];
            Ah[2] = *(const uint32_t*)&sA_hi[r0 * QS + kb + qr + 8];
            Ah[3] = *(const uint32_t*)&sA_hi[(r0 + 8) * QS + kb + qr + 8];
            Al[0] = *(const uint32_t*)&sA_lo[r0 * QS + kb + qr];
            Al[1] = *(const uint32_t*)&sA_lo[(r0 + 8) * QS + kb + qr];
            Al[2] = *(const uint32_t*)&sA_lo[r0 * QS + kb + qr + 8];
            Al[3] = *(const uint32_t*)&sA_lo[(r0 + 8) * QS + kb + qr + 8];
#pragma unroll
            for (int jf = 0; jf < 8; jf++) {
                int jn = (jf * 8 + gq) * QS + kb + qr;
                uint32_t bh0 = *(const uint32_t*)&sB_hi[jn];
                uint32_t bh1 = *(const uint32_t*)&sB_hi[jn + 8];
                uint32_t bl0 = *(const uint32_t*)&sB_lo[jn];
                uint32_t bl1 = *(const uint32_t*)&sB_lo[jn + 8];
                mma16816(Oc[jf], Ah, bh0, bh1);
                mma16816(Oc[jf], Ah, bl0, bl1);
                mma16816(Oc[jf], Al, bh0, bh1);
            }
        }
        __syncthreads();
    }

    // ---- epilogue: route to Q/K/V scratch ----
    float* dst;
    int jo = j0;
    if (g == 0)      dst = g_Q1;
    else if (g == 2) dst = g_Q2;
    else if (g == 1) { if (j0 < 256) dst = g_K1; else { dst = g_V1; jo = j0 - 256; } }
    else             { if (j0 < 256) dst = g_K2; else { dst = g_V2; jo = j0 - 256; } }

    const int rg = n0 + w * 16 + gq;
#pragma unroll
    for (int jf = 0; jf < 8; jf++) {
        int c = jf * 8 + qr;
        *(float2*)&dst[((size_t)b * NSEQ + rg) * CDIM + jo + c] =
            make_float2(Oc[jf][0], Oc[jf][1]);
        *(float2*)&dst[((size_t)b * NSEQ + rg + 8) * CDIM + jo + c] =
            make_float2(Oc[jf][2], Oc[jf][3]);
    }
}

// ===========================================================================
// Kernel 2: flash attention on mma.sync.m16n8k16 (validated R12: works),
// now with register prefetch of next tile's K/V to hide global latency.
// ===========================================================================
#define KS_STRIDE 40
#define VT_STRIDE 72

__global__ __launch_bounds__(128) void attn_mma(const float* __restrict__ umask)
{
    __shared__ alignas(16) uint16_t sK_hi[KT * KS_STRIDE];
    __shared__ alignas(16) uint16_t sK_lo[KT * KS_STRIDE];
    __shared__ alignas(16) uint16_t sV_hi[HDIM * VT_STRIDE];
    __shared__ alignas(16) uint16_t sV_lo[HDIM * VT_STRIDE];

    const int tid  = threadIdx.x;
    const int lane = tid & 31;
    const int w    = tid >> 5;
    const int qt = blockIdx.x;
    const int hh = blockIdx.y;
    const int z  = blockIdx.z;
    const int b  = z >> 1;
    const int br = z & 1;

    const float* Q = br ? g_Q2 : g_Q1;
    const float* K = br ? g_K2 : g_K1;
    const float* V = br ? g_V2 : g_V1;
    float*       O = br ? g_O2 : g_O1;

    const int n0 = qt * QT;
    const int g  = lane >> 2;
    const int qr = (lane & 3) * 2;
    const int r0 = n0 + w * 16 + g;
    const int r1 = r0 + 8;

    float uw0 = 1.f, uw1 = 1.f;
    if (br == 0) {
        uw0 = 1.0f / (umask[b * NSEQ + r0] + 1e-6f);
        uw1 = 1.0f / (umask[b * NSEQ + r1] + 1e-6f);
    }

    // Q A-fragments, hi/lo, ATT_SCALE folded
    uint32_t Ah[2][4], Al[2][4];
    {
        const float* q0 = Q + ((size_t)b * NSEQ + r0) * CDIM + hh * HDIM;
        const float* q1 = Q + ((size_t)b * NSEQ + r1) * CDIM + hh * HDIM;
#pragma unroll
        for (int s = 0; s < 2; s++) {
            int db = s * 16 + qr;
            float2 f; uint2 u;
            f = *(const float2*)(q0 + db);
            u = split2(f.x * ATT_SCALE, f.y * ATT_SCALE); Ah[s][0] = u.x; Al[s][0] = u.y;
            f = *(const float2*)(q1 + db);
            u = split2(f.x * ATT_SCALE, f.y * ATT_SCALE); Ah[s][1] = u.x; Al[s][1] = u.y;
            f = *(const float2*)(q0 + db + 8);
            u = split2(f.x * ATT_SCALE, f.y * ATT_SCALE); Ah[s][2] = u.x; Al[s][2] = u.y;
            f = *(const float2*)(q1 + db + 8);
            u = split2(f.x * ATT_SCALE, f.y * ATT_SCALE); Ah[s][3] = u.x; Al[s][3] = u.y;
        }
    }

    float m0 = -1e30f, m1 = -1e30f, l0 = 0.f, l1 = 0.f;
    float Oc[4][4];
#pragma unroll
    for (int f = 0; f < 4; f++)
#pragma unroll
        for (int i = 0; i < 4; i++) Oc[f][i] = 0.f;

    // ---- prefetch machinery: this thread's K/V rows for a tile ----
    const int key = tid >> 1, dh = (tid & 1) * 16;
    float4 kf[4], vf[4];
    {
        const size_t kb0 = ((size_t)b * NSEQ) * CDIM + hh * HDIM;
        const float4* ks = (const float4*)(K + kb0 + (size_t)key * CDIM + dh);
        const float4* vs = (const float4*)(V + kb0 + (size_t)key * CDIM + dh);
#pragma unroll
        for (int i = 0; i < 4; i++) { kf[i] = ks[i]; vf[i] = vs[i]; }
    }

    for (int kt = 0; kt < NKT; kt++) {
        // ---- split + store prefetched tile to smem ----
        {
            uint32_t* kh = (uint32_t*)(sK_hi + key * KS_STRIDE + dh);
            uint32_t* kl = (uint32_t*)(sK_lo + key * KS_STRIDE + dh);
#pragma unroll
            for (int i = 0; i < 4; i++) {
                float4 f = kf[i];
                uint2 u01 = split2(f.x, f.y), u23 = split2(f.z, f.w);
                kh[i * 2] = u01.x; kh[i * 2 + 1] = u23.x;
                kl[i * 2] = u01.y; kl[i * 2 + 1] = u23.y;
                float4 v = vf[i];
                int d = dh + i * 4;
                uint2 w01 = split2(v.x, v.y), w23 = split2(v.z, v.w);
                sV_hi[(d + 0) * VT_STRIDE + key] = (uint16_t)(w01.x & 0xFFFF);
                sV_hi[(d + 1) * VT_STRIDE + key] = (uint16_t)(w01.x >> 16);
                sV_hi[(d + 2) * VT_STRIDE + key] = (uint16_t)(w23.x & 0xFFFF);
                sV_hi[(d + 3) * VT_STRIDE + key] = (uint16_t)(w23.x >> 16);
                sV_lo[(d + 0) * VT_STRIDE + key] = (uint16_t)(w01.y & 0xFFFF);
                sV_lo[(d + 1) * VT_STRIDE + key] = (uint16_t)(w01.y >> 16);
                sV_lo[(d + 2) * VT_STRIDE + key] = (uint16_t)(w23.y & 0xFFFF);
                sV_lo[(d + 3) * VT_STRIDE + key] = (uint16_t)(w23.y >> 16);
            }
        }
        __syncthreads();

        // ---- issue next tile's global loads (latency hidden by compute) ----
        if (kt + 1 < NKT) {
            const size_t kbn = ((size_t)b * NSEQ + (kt + 1) * KT) * CDIM + hh * HDIM;
            const float4* ks = (const float4*)(K + kbn + (size_t)key * CDIM + dh);
            const float4* vs = (const float4*)(V + kbn + (size_t)key * CDIM + dh);
#pragma unroll
            for (int i = 0; i < 4; i++) { kf[i] = ks[i]; vf[i] = vs[i]; }
        }

        // ---- S = Q K^T (AhKh + AhKl + AlKh), fp32 accum ----
        float Sc[8][4];
#pragma unroll
        for (int f = 0; f < 8; f++)
#pragma unroll
            for (int i = 0; i < 4; i++) Sc[f][i] = 0.f;
#pragma unroll
        for (int f = 0; f < 8; f++) {
#pragma unroll
            for (int s = 0; s < 2; s++) {
                int idx = (f * 8 + g) * KS_STRIDE + s * 16 + qr;
                uint32_t bh0 = *(const uint32_t*)(sK_hi + idx);
                uint32_t bh1 = *(const uint32_t*)(sK_hi + idx + 8);
                uint32_t bl0 = *(const uint32_t*)(sK_lo + idx);
                uint32_t bl1 = *(const uint32_t*)(sK_lo + idx + 8);
                mma16816(Sc[f], Ah[s], bh0, bh1);
                mma16816(Sc[f], Ah[s], bl0, bl1);
                mma16816(Sc[f], Al[s], bh0, bh1);
            }
        }

        // ---- uw scale + online softmax ----
        float mx0 = -1e30f, mx1 = -1e30f;
#pragma unroll
        for (int f = 0; f < 8; f++) {
            Sc[f][0] *= uw0; Sc[f][1] *= uw0;
            Sc[f][2] *= uw1; Sc[f][3] *= uw1;
            mx0 = fmaxf(mx0, fmaxf(Sc[f][0], Sc[f][1]));
            mx1 = fmaxf(mx1, fmaxf(Sc[f][2], Sc[f][3]));
        }
        mx0 = fmaxf(mx0, __shfl_xor_sync(0xffffffffu, mx0, 1));
        mx0 = fmaxf(mx0, __shfl_xor_sync(0xffffffffu, mx0, 2));
        mx1 = fmaxf(mx1, __shfl_xor_sync(0xffffffffu, mx1, 1));
        mx1 = fmaxf(mx1, __shfl_xor_sync(0xffffffffu, mx1, 2));
        float mn0 = fmaxf(m0, mx0), mn1 = fmaxf(m1, mx1);
        float a0 = __expf(m0 - mn0), a1 = __expf(m1 - mn1);
        m0 = mn0; m1 = mn1;
#pragma unroll
        for (int f = 0; f < 4; f++) {
            Oc[f][0] *= a0; Oc[f][1] *= a0;
            Oc[f][2] *= a1; Oc[f][3] *= a1;
        }
        float s0 = 0.f, s1 = 0.f;
#pragma unroll
        for (int f = 0; f < 8; f++) {
            Sc[f][0] = __expf(Sc[f][0] - m0); s0 += Sc[f][0];
            Sc[f][1] = __expf(Sc[f][1] - m0); s0 += Sc[f][1];
            Sc[f][2] = __expf(Sc[f][2] - m1); s1 += Sc[f][2];
            Sc[f][3] = __expf(Sc[f][3] - m1); s1 += Sc[f][3];
        }
        s0 += __shfl_xor_sync(0xffffffffu, s0, 1);
        s0 += __shfl_xor_sync(0xffffffffu, s0, 2);
        s1 += __shfl_xor_sync(0xffffffffu, s1, 1);
        s1 += __shfl_xor_sync(0xffffffffu, s1, 2);
        l0 = l0 * a0 + s0;
        l1 = l1 * a1 + s1;

        // ---- O += P V (S C-frags as PV A-frags, register-resident P) ----
#pragma unroll
        for (int j = 0; j < 4; j++) {
            uint32_t Ph[4], Pl[4];
            uint2 u;
            u = split2(Sc[2 * j][0], Sc[2 * j][1]);         Ph[0] = u.x; Pl[0] = u.y;
            u = split2(Sc[2 * j][2], Sc[2 * j][3]);         Ph[1] = u.x; Pl[1] = u.y;
            u = split2(Sc[2 * j + 1][0], Sc[2 * j + 1][1]); Ph[2] = u.x; Pl[2] = u.y;
            u = split2(Sc[2 * j + 1][2], Sc[2 * j + 1][3]); Ph[3] = u.x; Pl[3] = u.y;
#pragma unroll
            for (int f = 0; f < 4; f++) {
                int idx = (f * 8 + g) * VT_STRIDE + j * 16 + qr;
                uint32_t bh0 = *(const uint32_t*)(sV_hi + idx);
                uint32_t bh1 = *(const uint32_t*)(sV_hi + idx + 8);
                uint32_t bl0 = *(const uint32_t*)(sV_lo + idx);
                uint32_t bl1 = *(const uint32_t*)(sV_lo + idx + 8);
                mma16816(Oc[f], Ph, bh0, bh1);
                mma16816(Oc[f], Ph, bl0, bl1);
                mma16816(Oc[f], Pl, bh0, bh1);
            }
        }
        __syncthreads();
    }

    // ---- epilogue ----
    const float i0 = 1.0f / l0, i1 = 1.0f / l1;
    float* o0 = O + ((size_t)b * NSEQ + r0) * CDIM + hh * HDIM;
    float* o1 = O + ((size_t)b * NSEQ + r1) * CDIM + hh * HDIM;
#pragma unroll
    for (int f = 0; f < 4; f++) {
        int c = f * 8 + qr;
        *(float2*)(o0 + c) = make_float2(Oc[f][0] * i0, Oc[f][1] * i0);
        *(float2*)(o1 + c) = make_float2(Oc[f][2] * i1, Oc[f][3] * i1);
    }
}

// ===========================================================================
// Kernel 3: output projection + bias, written transposed to (B,C,H,W)
// ===========================================================================
__global__ __launch_bounds__(256) void gemm_proj(
    const float* __restrict__ Wpi, const float* __restrict__ bpi,
    const float* __restrict__ Wpr, const float* __restrict__ bpr,
    float* __restrict__ out)
{
    const int z = blockIdx.z;
    const int b = z >> 1;
    const int br = z & 1;
    const float* A = (br ? g_O2 : g_O1) + (size_t)b * NSEQ * CDIM;
    const float* W = br ? Wpr : Wpi;
    const float* bias = br ? bpr : bpi;
    float* O = out + (br ? (size_t)BATCH * CDIM * NSEQ : 0) + (size_t)b * CDIM * NSEQ;

    const int n0 = blockIdx.x * 64;
    const int j0 = blockIdx.y * 64;

    __shared__ float As[64][17];
    __shared__ float Bs[16][64];

    const int tid = threadIdx.x;
    const int tx = tid & 15, ty = tid >> 4;

    float acc[4][4];
#pragma unroll
    for (int i = 0; i < 4; i++)
#pragma unroll
        for (int j = 0; j < 4; j++) acc[i][j] = 0.f;

    for (int k0 = 0; k0 < CDIM; k0 += 16) {
#pragma unroll
        for (int it = 0; it < 4; it++) {
            int idx = tid + it * 256;
            int mm = idx >> 4, kk = idx & 15;
            As[mm][kk] = A[(size_t)(n0 + mm) * CDIM + k0 + kk];
        }
#pragma unroll
        for (int it = 0; it < 4; it++) {
            int idx = tid + it * 256;
            int kk = idx >> 6, jj = idx & 63;
            Bs[kk][jj] = W[(k0 + kk) * CDIM + j0 + jj];
        }
        __syncthreads();
#pragma unroll
        for (int kk = 0; kk < 16; kk++) {
            float4 b4 = *(const float4*)&Bs[kk][tx * 4];
            float bv[4] = {b4.x, b4.y, b4.z, b4.w};
            float av[4];
#pragma unroll
            for (int i = 0; i < 4; i++) av[i] = As[ty * 4 + i][kk];
#pragma unroll
            for (int i = 0; i < 4; i++)
#pragma unroll
                for (int j = 0; j < 4; j++)
                    acc[i][j] = fmaf(av[i], bv[j], acc[i][j]);
        }
        __syncthreads();
    }

#pragma unroll
    for (int jj = 0; jj < 4; jj++) {
        int j = j0 + tx * 4 + jj;
        float bval = bias[j];
        float4 v = make_float4(acc[0][jj] + bval, acc[1][jj] + bval,
                               acc[2][jj] + bval, acc[3][jj] + bval);
        *(float4*)&O[(size_t)j * NSEQ + n0 + ty * 4] = v;
    }
}

// ===========================================================================
extern "C" void kernel_launch(void* const* d_in, const int* in_sizes, int n_in,
                              void* d_out, int out_size)
{
    const float* img   = (const float*)d_in[0];
    const float* radar = (const float*)d_in[1];
    const float* mask  = (const float*)d_in[2];
    const float* Wqi   = (const float*)d_in[3];
    const float* Wkvr  = (const float*)d_in[4];
    const float* Wqr   = (const float*)d_in[5];
    const float* Wkvi  = (const float*)d_in[6];
    const float* Wpi   = (const float*)d_in[7];
    const float* bpi   = (const float*)d_in[8];
    const float* Wpr   = (const float*)d_in[9];
    const float* bpr   = (const float*)d_in[10];
    float* out = (float*)d_out;

    gemm_qkv_mma<<<dim3(NSEQ / 64, 8, BATCH * 4), 128>>>(img, radar, Wqi, Wkvr, Wqr, Wkvi);
    attn_mma<<<dim3(NSEQ / QT, NHEADS, BATCH * 2), 128>>>(mask);
    gemm_proj<<<dim3(NSEQ / 64, CDIM / 64, BATCH * 2), 256>>>(Wpi, bpi, Wpr, bpr, out);
}